// round 1
// baseline (speedup 1.0000x reference)
#include <cuda_runtime.h>
#include <cuda_bf16.h>

// ---------------------------------------------------------------------------
// 3-layer GCN: h = D^-1/2 (A+I) D^-1/2 (X W) + b, relu after layers 1,2.
// Strategy:
//   1. Build CSR-by-dst per launch (histogram + single-block scan + scatter).
//   2. GEMM (fp32 tiled SGEMM) with epilogue scale: g = (X W) * dinv[row].
//   3. Warp-per-node pull aggregation: out[d] = dinv[d]*(g[d]+sum g[src]) + b.
// Feature matrices (25.6MB) are L2-resident; all gathers are coalesced
// 512B/256B warp reads.
// ---------------------------------------------------------------------------

#define MAXN 50000
#define MAXE 800000

__device__ float g_h[(size_t)MAXN * 128];   // GEMM output (row-scaled)
__device__ float g_t[(size_t)MAXN * 128];   // aggregation output / next input
__device__ float g_dinv[MAXN];
__device__ int   g_cnt[MAXN];
__device__ int   g_off[MAXN + 1];
__device__ int   g_cur[MAXN];
__device__ int   g_srcs[MAXE];
__device__ int   g_is64;

// ---------------------------------------------------------------------------
// Edge index dtype detection: if int64, the high 32-bit words (odd int32
// indices, little-endian) of values in [0, 50000) are all zero.
// ---------------------------------------------------------------------------
__global__ void detect_kernel(const void* edges, int E) {
    __shared__ int nz;
    if (threadIdx.x == 0) nz = 0;
    __syncthreads();
    const int* w = (const int*)edges;
    int cnt = 0;
    for (int i = threadIdx.x; i < 2048; i += blockDim.x) {
        int idx = 2 * i + 1;          // odd word, always < 2*E for both dtypes
        if (idx < 2 * E && w[idx] != 0) cnt++;
    }
    atomicAdd(&nz, cnt);
    __syncthreads();
    if (threadIdx.x == 0) g_is64 = (nz == 0) ? 1 : 0;
}

__device__ __forceinline__ int edge_val(const void* p, long long idx) {
    if (g_is64) return (int)((const long long*)p)[idx];
    return ((const int*)p)[idx];
}

__global__ void init_kernel(int n) {
    int i = blockIdx.x * blockDim.x + threadIdx.x;
    if (i < n) { g_cnt[i] = 0; g_cur[i] = 0; }
}

__global__ void hist_kernel(const void* edges, int E) {
    int e = blockIdx.x * blockDim.x + threadIdx.x;
    if (e < E) {
        int d = edge_val(edges, (long long)E + e);
        atomicAdd(&g_cnt[d], 1);
    }
}

// Single-block exclusive scan of g_cnt -> g_off, plus dinv = rsqrt(cnt+1).
__global__ void scan_kernel(int n) {
    __shared__ int partial[1024];
    int tid = threadIdx.x;
    int chunk = (n + 1023) / 1024;
    int b = tid * chunk;
    int e2 = min(n, b + chunk);
    int sum = 0;
    for (int i = b; i < e2; i++) sum += g_cnt[i];
    partial[tid] = sum;
    __syncthreads();
    for (int ofs = 1; ofs < 1024; ofs <<= 1) {
        int v = (tid >= ofs) ? partial[tid - ofs] : 0;
        __syncthreads();
        partial[tid] += v;
        __syncthreads();
    }
    int run = (tid == 0) ? 0 : partial[tid - 1];
    for (int i = b; i < e2; i++) {
        g_off[i] = run;
        run += g_cnt[i];
        g_dinv[i] = rsqrtf((float)(g_cnt[i] + 1));
    }
    if (tid == 0) g_off[n] = partial[1023];
}

__global__ void scatter_kernel(const void* edges, int E) {
    int e = blockIdx.x * blockDim.x + threadIdx.x;
    if (e < E) {
        int d = edge_val(edges, (long long)E + e);
        int s = edge_val(edges, e);
        int pos = g_off[d] + atomicAdd(&g_cur[d], 1);
        g_srcs[pos] = s;
    }
}

// ---------------------------------------------------------------------------
// Tiled SGEMM: C[M,N] = (A[M,128] @ B[128,N]) * dinv[row]
// BM=128, BK=16, TM=8; BN/TN give 256 threads in both instantiations.
// ---------------------------------------------------------------------------
template <int BN, int TN>
__global__ __launch_bounds__(256) void gemm_scale_kernel(
    const float* __restrict__ A, const float* __restrict__ B,
    float* __restrict__ C, int M, int N)
{
    constexpr int BM = 128, BK = 16, TM = 8, K = 128;
    constexpr int THREADS = (BM / TM) * (BN / TN);
    __shared__ float As[BK][BM];
    __shared__ float Bs[BK][BN];

    const int block_row = blockIdx.x * BM;
    const int tid = threadIdx.x;
    const int tcol = tid % (BN / TN);
    const int trow = tid / (BN / TN);

    float acc[TM][TN];
#pragma unroll
    for (int i = 0; i < TM; i++)
#pragma unroll
        for (int j = 0; j < TN; j++) acc[i][j] = 0.f;

    for (int kt = 0; kt < K; kt += BK) {
        constexpr int A_f4 = BM * BK / 4;
#pragma unroll
        for (int i = tid; i < A_f4; i += THREADS) {
            int r  = i / (BK / 4);
            int c4 = i % (BK / 4);
            float4 v = make_float4(0.f, 0.f, 0.f, 0.f);
            if (block_row + r < M)
                v = *(const float4*)&A[(size_t)(block_row + r) * K + kt + c4 * 4];
            As[c4 * 4 + 0][r] = v.x;
            As[c4 * 4 + 1][r] = v.y;
            As[c4 * 4 + 2][r] = v.z;
            As[c4 * 4 + 3][r] = v.w;
        }
        constexpr int B_f4 = BK * BN / 4;
#pragma unroll
        for (int i = tid; i < B_f4; i += THREADS) {
            int r  = i / (BN / 4);
            int c4 = i % (BN / 4);
            *(float4*)&Bs[r][c4 * 4] = *(const float4*)&B[(size_t)(kt + r) * N + c4 * 4];
        }
        __syncthreads();
#pragma unroll
        for (int kk = 0; kk < BK; kk++) {
            float a[TM], b[TN];
#pragma unroll
            for (int i = 0; i < TM; i++) a[i] = As[kk][trow * TM + i];
#pragma unroll
            for (int j = 0; j < TN; j++) b[j] = Bs[kk][tcol * TN + j];
#pragma unroll
            for (int i = 0; i < TM; i++)
#pragma unroll
                for (int j = 0; j < TN; j++) acc[i][j] += a[i] * b[j];
        }
        __syncthreads();
    }

#pragma unroll
    for (int i = 0; i < TM; i++) {
        int r = block_row + trow * TM + i;
        if (r >= M) break;
        float s = g_dinv[r];
#pragma unroll
        for (int j = 0; j < TN; j += 4) {
            float4 v;
            v.x = acc[i][j + 0] * s;
            v.y = acc[i][j + 1] * s;
            v.z = acc[i][j + 2] * s;
            v.w = acc[i][j + 3] * s;
            *(float4*)&C[(size_t)r * N + tcol * TN + j] = v;
        }
    }
}

// ---------------------------------------------------------------------------
// Warp-per-node aggregation, D=128 (float4/lane).
// out[d] = maybe_relu( dinv[d] * (g[d] + sum_{s->d} g[s]) + bias )
// ---------------------------------------------------------------------------
template <bool RELU>
__global__ void aggregate128_kernel(const float* __restrict__ g,
                                    const float* __restrict__ bias,
                                    float* __restrict__ out, int n)
{
    int warp = (blockIdx.x * blockDim.x + threadIdx.x) >> 5;
    if (warp >= n) return;
    int lane = threadIdx.x & 31;
    const float4* g4 = (const float4*)g;

    float4 acc = g4[(size_t)warp * 32 + lane];   // self-loop term
    int e = g_off[warp];
    int end = g_off[warp + 1];
    while (e < end) {
        int m = min(32, end - e);
        int s = (lane < m) ? g_srcs[e + lane] : 0;
#pragma unroll 4
        for (int j = 0; j < m; j++) {
            int sj = __shfl_sync(0xffffffffu, s, j);
            float4 v = g4[(size_t)sj * 32 + lane];
            acc.x += v.x; acc.y += v.y; acc.z += v.z; acc.w += v.w;
        }
        e += m;
    }
    float sc = g_dinv[warp];
    float4 bv = ((const float4*)bias)[lane];
    float4 o;
    o.x = acc.x * sc + bv.x;
    o.y = acc.y * sc + bv.y;
    o.z = acc.z * sc + bv.z;
    o.w = acc.w * sc + bv.w;
    if (RELU) {
        o.x = fmaxf(o.x, 0.f); o.y = fmaxf(o.y, 0.f);
        o.z = fmaxf(o.z, 0.f); o.w = fmaxf(o.w, 0.f);
    }
    ((float4*)out)[(size_t)warp * 32 + lane] = o;
}

// D=64 variant (float2/lane), no relu (final layer).
__global__ void aggregate64_kernel(const float* __restrict__ g,
                                   const float* __restrict__ bias,
                                   float* __restrict__ out, int n)
{
    int warp = (blockIdx.x * blockDim.x + threadIdx.x) >> 5;
    if (warp >= n) return;
    int lane = threadIdx.x & 31;
    const float2* g2 = (const float2*)g;

    float2 acc = g2[(size_t)warp * 32 + lane];
    int e = g_off[warp];
    int end = g_off[warp + 1];
    while (e < end) {
        int m = min(32, end - e);
        int s = (lane < m) ? g_srcs[e + lane] : 0;
#pragma unroll 4
        for (int j = 0; j < m; j++) {
            int sj = __shfl_sync(0xffffffffu, s, j);
            float2 v = g2[(size_t)sj * 32 + lane];
            acc.x += v.x; acc.y += v.y;
        }
        e += m;
    }
    float sc = g_dinv[warp];
    float2 bv = ((const float2*)bias)[lane];
    float2 o;
    o.x = acc.x * sc + bv.x;
    o.y = acc.y * sc + bv.y;
    ((float2*)out)[(size_t)warp * 32 + lane] = o;
}

// ---------------------------------------------------------------------------
extern "C" void kernel_launch(void* const* d_in, const int* in_sizes, int n_in,
                              void* d_out, int out_size) {
    const float* x  = (const float*)d_in[0];
    const void*  ei = d_in[1];
    const float* W1 = (const float*)d_in[2];
    const float* b1 = (const float*)d_in[3];
    const float* W2 = (const float*)d_in[4];
    const float* b2 = (const float*)d_in[5];
    const float* W3 = (const float*)d_in[6];
    const float* b3 = (const float*)d_in[7];
    float* out = (float*)d_out;

    const int n = in_sizes[0] / 128;   // 50000
    const int E = in_sizes[1] / 2;     // 800000

    float *h = nullptr, *t = nullptr;
    cudaGetSymbolAddress((void**)&h, g_h);
    cudaGetSymbolAddress((void**)&t, g_t);

    // ---- CSR build ----
    init_kernel<<<(n + 255) / 256, 256>>>(n);
    detect_kernel<<<1, 256>>>(ei, E);
    hist_kernel<<<(E + 255) / 256, 256>>>(ei, E);
    scan_kernel<<<1, 1024>>>(n);
    scatter_kernel<<<(E + 255) / 256, 256>>>(ei, E);

    const int gx = (n + 127) / 128;
    const int agg_blocks = (n * 32 + 255) / 256;

    // ---- layer 1 ----
    gemm_scale_kernel<128, 8><<<dim3(gx, 1), 256>>>(x, W1, h, n, 128);
    aggregate128_kernel<true><<<agg_blocks, 256>>>(h, b1, t, n);
    // ---- layer 2 ----
    gemm_scale_kernel<128, 8><<<dim3(gx, 1), 256>>>(t, W2, h, n, 128);
    aggregate128_kernel<true><<<agg_blocks, 256>>>(h, b2, t, n);
    // ---- layer 3 ----
    gemm_scale_kernel<64, 4><<<dim3(gx, 1), 256>>>(t, W3, h, n, 64);
    aggregate64_kernel<<<agg_blocks, 256>>>(h, b3, out, n);
}

// round 3
// speedup vs baseline: 1.2802x; 1.2802x over previous
#include <cuda_runtime.h>
#include <cuda_bf16.h>

// ---------------------------------------------------------------------------
// 3-layer GCN: h = D^-1/2 (A+I) D^-1/2 (X W) + b, relu after layers 1,2.
//   1. CSR-by-dst per launch: zero + hist + 3-phase multi-block scan + scatter.
//   2. fp32 tiled SGEMM with epilogue scale: g = (X W) * dinv[row].
//   3. Warp-per-node pull aggregation: out[d] = dinv[d]*(g[d]+sum g[src]) + b.
// ---------------------------------------------------------------------------

#define MAXN 50000
#define MAXE 800000
#define SCAN_B 1024
#define SCAN_GRID ((MAXN + SCAN_B - 1) / SCAN_B)   // 49

__device__ float g_h[(size_t)MAXN * 128];   // GEMM output (row-scaled)
__device__ float g_t[(size_t)MAXN * 128];   // aggregation output / next input
__device__ float g_dinv[MAXN];
__device__ int   g_cnt[MAXN];
__device__ int   g_off[MAXN + 1];
__device__ int   g_cur[MAXN];
__device__ int   g_srcs[MAXE];
__device__ int   g_bsum[SCAN_GRID + 1];
__device__ int   g_is64;

__global__ void init_kernel(int n) {
    int i = blockIdx.x * blockDim.x + threadIdx.x;
    if (i < n) { g_cnt[i] = 0; g_cur[i] = 0; }
}

// ---------------------------------------------------------------------------
// Edge dtype detection: int64 values < 50000 have all-zero high words.
// ---------------------------------------------------------------------------
__global__ void detect_kernel(const void* edges, int E) {
    __shared__ int nz;
    if (threadIdx.x == 0) nz = 0;
    __syncthreads();
    const int* w = (const int*)edges;
    int cnt = 0;
    for (int i = threadIdx.x; i < 2048; i += blockDim.x) {
        int idx = 2 * i + 1;
        if (idx < 2 * E && w[idx] != 0) cnt++;
    }
    atomicAdd(&nz, cnt);
    __syncthreads();
    if (threadIdx.x == 0) g_is64 = (nz == 0) ? 1 : 0;
}

__device__ __forceinline__ int edge_val(const void* p, long long idx) {
    if (g_is64) return (int)((const long long*)p)[idx];
    return ((const int*)p)[idx];
}

__global__ void hist_kernel(const void* edges, int E) {
    int e = blockIdx.x * blockDim.x + threadIdx.x;
    if (e < E) {
        int d = edge_val(edges, (long long)E + e);
        atomicAdd(&g_cnt[d], 1);
    }
}

// ---------------------------------------------------------------------------
// Multi-block scan, phase A: per-block exclusive scan of g_cnt into g_off,
// block totals into g_bsum, dinv = rsqrt(cnt+1).
// ---------------------------------------------------------------------------
__global__ __launch_bounds__(SCAN_B) void scanA_kernel(int n) {
    __shared__ int wsum[32];
    int gid = blockIdx.x * SCAN_B + threadIdx.x;
    int lane = threadIdx.x & 31;
    int wid = threadIdx.x >> 5;

    int c = (gid < n) ? g_cnt[gid] : 0;
    if (gid < n) g_dinv[gid] = rsqrtf((float)(c + 1));

    // inclusive warp scan
    int v = c;
#pragma unroll
    for (int o = 1; o < 32; o <<= 1) {
        int u = __shfl_up_sync(0xffffffffu, v, o);
        if (lane >= o) v += u;
    }
    if (lane == 31) wsum[wid] = v;
    __syncthreads();
    if (wid == 0) {
        int w = (lane < SCAN_B / 32) ? wsum[lane] : 0;
#pragma unroll
        for (int o = 1; o < 32; o <<= 1) {
            int u = __shfl_up_sync(0xffffffffu, w, o);
            if (lane >= o) w += u;
        }
        wsum[lane] = w;
    }
    __syncthreads();
    int base = (wid == 0) ? 0 : wsum[wid - 1];
    int excl = base + v - c;               // exclusive within block
    if (gid < n) g_off[gid] = excl;
    if (threadIdx.x == SCAN_B - 1) g_bsum[blockIdx.x] = base + v;
}

// Phase B: scan the 49 block sums (exclusive), set g_off[n]=E.
__global__ void scanB_kernel(int n, int E) {
    int lane = threadIdx.x;
    __shared__ int buf[64];
    buf[lane] = (lane < SCAN_GRID) ? g_bsum[lane] : 0;
    __syncthreads();
    if (lane == 0) {
        int run = 0;
        for (int i = 0; i < 64; i++) { int t = buf[i]; buf[i] = run; run += t; }
    }
    __syncthreads();
    if (lane < SCAN_GRID) g_bsum[lane] = buf[lane];
    if (lane == 0) g_off[n] = E;
}

// Phase C: uniform add.
__global__ __launch_bounds__(SCAN_B) void scanC_kernel(int n) {
    int gid = blockIdx.x * SCAN_B + threadIdx.x;
    if (gid < n && blockIdx.x > 0) g_off[gid] += g_bsum[blockIdx.x];
}

__global__ void scatter_kernel(const void* edges, int E) {
    int e = blockIdx.x * blockDim.x + threadIdx.x;
    if (e < E) {
        int d = edge_val(edges, (long long)E + e);
        int s = edge_val(edges, e);
        int pos = g_off[d] + atomicAdd(&g_cur[d], 1);
        g_srcs[pos] = s;
    }
}

// ---------------------------------------------------------------------------
// Tiled SGEMM: C[M,N] = (A[M,128] @ B[128,N]) * dinv[row]
// ---------------------------------------------------------------------------
template <int BN, int TN>
__global__ __launch_bounds__(256) void gemm_scale_kernel(
    const float* __restrict__ A, const float* __restrict__ B,
    float* __restrict__ C, int M, int N)
{
    constexpr int BM = 128, BK = 16, TM = 8, K = 128;
    constexpr int THREADS = (BM / TM) * (BN / TN);
    __shared__ float As[BK][BM];
    __shared__ float Bs[BK][BN];

    const int block_row = blockIdx.x * BM;
    const int tid = threadIdx.x;
    const int tcol = tid % (BN / TN);
    const int trow = tid / (BN / TN);

    float acc[TM][TN];
#pragma unroll
    for (int i = 0; i < TM; i++)
#pragma unroll
        for (int j = 0; j < TN; j++) acc[i][j] = 0.f;

    for (int kt = 0; kt < K; kt += BK) {
        constexpr int A_f4 = BM * BK / 4;
#pragma unroll
        for (int i = tid; i < A_f4; i += THREADS) {
            int r  = i / (BK / 4);
            int c4 = i % (BK / 4);
            float4 v = make_float4(0.f, 0.f, 0.f, 0.f);
            if (block_row + r < M)
                v = *(const float4*)&A[(size_t)(block_row + r) * K + kt + c4 * 4];
            As[c4 * 4 + 0][r] = v.x;
            As[c4 * 4 + 1][r] = v.y;
            As[c4 * 4 + 2][r] = v.z;
            As[c4 * 4 + 3][r] = v.w;
        }
        constexpr int B_f4 = BK * BN / 4;
#pragma unroll
        for (int i = tid; i < B_f4; i += THREADS) {
            int r  = i / (BN / 4);
            int c4 = i % (BN / 4);
            *(float4*)&Bs[r][c4 * 4] = *(const float4*)&B[(size_t)(kt + r) * N + c4 * 4];
        }
        __syncthreads();
#pragma unroll
        for (int kk = 0; kk < BK; kk++) {
            float a[TM], b[TN];
#pragma unroll
            for (int i = 0; i < TM; i++) a[i] = As[kk][trow * TM + i];
#pragma unroll
            for (int j = 0; j < TN; j++) b[j] = Bs[kk][tcol * TN + j];
#pragma unroll
            for (int i = 0; i < TM; i++)
#pragma unroll
                for (int j = 0; j < TN; j++) acc[i][j] += a[i] * b[j];
        }
        __syncthreads();
    }

#pragma unroll
    for (int i = 0; i < TM; i++) {
        int r = block_row + trow * TM + i;
        if (r >= M) break;
        float s = g_dinv[r];
#pragma unroll
        for (int j = 0; j < TN; j += 4) {
            float4 v;
            v.x = acc[i][j + 0] * s;
            v.y = acc[i][j + 1] * s;
            v.z = acc[i][j + 2] * s;
            v.w = acc[i][j + 3] * s;
            *(float4*)&C[(size_t)r * N + tcol * TN + j] = v;
        }
    }
}

// ---------------------------------------------------------------------------
// Warp-per-node aggregation.
// ---------------------------------------------------------------------------
template <bool RELU>
__global__ void aggregate128_kernel(const float* __restrict__ g,
                                    const float* __restrict__ bias,
                                    float* __restrict__ out, int n)
{
    int warp = (blockIdx.x * blockDim.x + threadIdx.x) >> 5;
    if (warp >= n) return;
    int lane = threadIdx.x & 31;
    const float4* g4 = (const float4*)g;

    float4 acc = g4[(size_t)warp * 32 + lane];   // self-loop term
    int e = g_off[warp];
    int end = g_off[warp + 1];
    while (e < end) {
        int m = min(32, end - e);
        int s = (lane < m) ? g_srcs[e + lane] : 0;
#pragma unroll 4
        for (int j = 0; j < m; j++) {
            int sj = __shfl_sync(0xffffffffu, s, j);
            float4 v = g4[(size_t)sj * 32 + lane];
            acc.x += v.x; acc.y += v.y; acc.z += v.z; acc.w += v.w;
        }
        e += m;
    }
    float sc = g_dinv[warp];
    float4 bv = ((const float4*)bias)[lane];
    float4 o;
    o.x = acc.x * sc + bv.x;
    o.y = acc.y * sc + bv.y;
    o.z = acc.z * sc + bv.z;
    o.w = acc.w * sc + bv.w;
    if (RELU) {
        o.x = fmaxf(o.x, 0.f); o.y = fmaxf(o.y, 0.f);
        o.z = fmaxf(o.z, 0.f); o.w = fmaxf(o.w, 0.f);
    }
    ((float4*)out)[(size_t)warp * 32 + lane] = o;
}

__global__ void aggregate64_kernel(const float* __restrict__ g,
                                   const float* __restrict__ bias,
                                   float* __restrict__ out, int n)
{
    int warp = (blockIdx.x * blockDim.x + threadIdx.x) >> 5;
    if (warp >= n) return;
    int lane = threadIdx.x & 31;
    const float2* g2 = (const float2*)g;

    float2 acc = g2[(size_t)warp * 32 + lane];
    int e = g_off[warp];
    int end = g_off[warp + 1];
    while (e < end) {
        int m = min(32, end - e);
        int s = (lane < m) ? g_srcs[e + lane] : 0;
#pragma unroll 4
        for (int j = 0; j < m; j++) {
            int sj = __shfl_sync(0xffffffffu, s, j);
            float2 v = g2[(size_t)sj * 32 + lane];
            acc.x += v.x; acc.y += v.y;
        }
        e += m;
    }
    float sc = g_dinv[warp];
    float2 bv = ((const float2*)bias)[lane];
    float2 o;
    o.x = acc.x * sc + bv.x;
    o.y = acc.y * sc + bv.y;
    ((float2*)out)[(size_t)warp * 32 + lane] = o;
}

// ---------------------------------------------------------------------------
extern "C" void kernel_launch(void* const* d_in, const int* in_sizes, int n_in,
                              void* d_out, int out_size) {
    const float* x  = (const float*)d_in[0];
    const void*  ei = d_in[1];
    const float* W1 = (const float*)d_in[2];
    const float* b1 = (const float*)d_in[3];
    const float* W2 = (const float*)d_in[4];
    const float* b2 = (const float*)d_in[5];
    const float* W3 = (const float*)d_in[6];
    const float* b3 = (const float*)d_in[7];
    float* out = (float*)d_out;

    const int n = in_sizes[0] / 128;   // 50000
    const int E = in_sizes[1] / 2;     // 800000

    float *h = nullptr, *t = nullptr;
    cudaGetSymbolAddress((void**)&h, g_h);
    cudaGetSymbolAddress((void**)&t, g_t);

    // ---- CSR build ----
    init_kernel<<<(n + 255) / 256, 256>>>(n);
    detect_kernel<<<1, 256>>>(ei, E);
    hist_kernel<<<(E + 255) / 256, 256>>>(ei, E);
    scanA_kernel<<<SCAN_GRID, SCAN_B>>>(n);
    scanB_kernel<<<1, 64>>>(n, E);
    scanC_kernel<<<SCAN_GRID, SCAN_B>>>(n);
    scatter_kernel<<<(E + 255) / 256, 256>>>(ei, E);

    const int gx = (n + 127) / 128;
    const int agg_blocks = (n * 32 + 255) / 256;

    // ---- layer 1 ----
    gemm_scale_kernel<128, 8><<<dim3(gx, 1), 256>>>(x, W1, h, n, 128);
    aggregate128_kernel<true><<<agg_blocks, 256>>>(h, b1, t, n);
    // ---- layer 2 ----
    gemm_scale_kernel<128, 8><<<dim3(gx, 1), 256>>>(t, W2, h, n, 128);
    aggregate128_kernel<true><<<agg_blocks, 256>>>(h, b2, t, n);
    // ---- layer 3 ----
    gemm_scale_kernel<64, 4><<<dim3(gx, 1), 256>>>(t, W3, h, n, 64);
    aggregate64_kernel<<<agg_blocks, 256>>>(h, b3, out, n);
}

// round 4
// speedup vs baseline: 1.4175x; 1.1072x over previous
#include <cuda_runtime.h>
#include <cuda_bf16.h>

// ---------------------------------------------------------------------------
// 3-layer GCN: h = D^-1/2 (A+I) D^-1/2 (X W) + b, relu after layers 1,2.
//   1. CSR-by-dst per launch: zero + hist + 3-phase multi-block scan + scatter.
//   2. fp32 tiled SGEMM using packed fma.rn.f32x2 (Blackwell FFMA2),
//      epilogue scale: g = (X W) * dinv[row].
//   3. Warp-per-node pull aggregation: out[d] = dinv[d]*(g[d]+sum g[src]) + b.
// ---------------------------------------------------------------------------

#define MAXN 50000
#define MAXE 800000
#define SCAN_B 1024
#define SCAN_GRID ((MAXN + SCAN_B - 1) / SCAN_B)   // 49

__device__ float g_h[(size_t)MAXN * 128];   // GEMM output (row-scaled)
__device__ float g_t[(size_t)MAXN * 128];   // aggregation output / next input
__device__ float g_dinv[MAXN];
__device__ int   g_cnt[MAXN];
__device__ int   g_off[MAXN + 1];
__device__ int   g_cur[MAXN];
__device__ int   g_srcs[MAXE];
__device__ int   g_bsum[SCAN_GRID + 1];
__device__ int   g_is64;

__global__ void init_kernel(int n) {
    int i = blockIdx.x * blockDim.x + threadIdx.x;
    if (i < n) { g_cnt[i] = 0; g_cur[i] = 0; }
}

// ---------------------------------------------------------------------------
// Edge dtype detection: int64 values < 50000 have all-zero high words.
// ---------------------------------------------------------------------------
__global__ void detect_kernel(const void* edges, int E) {
    __shared__ int nz;
    if (threadIdx.x == 0) nz = 0;
    __syncthreads();
    const int* w = (const int*)edges;
    int cnt = 0;
    for (int i = threadIdx.x; i < 2048; i += blockDim.x) {
        int idx = 2 * i + 1;
        if (idx < 2 * E && w[idx] != 0) cnt++;
    }
    atomicAdd(&nz, cnt);
    __syncthreads();
    if (threadIdx.x == 0) g_is64 = (nz == 0) ? 1 : 0;
}

__device__ __forceinline__ int edge_val(const void* p, long long idx) {
    if (g_is64) return (int)((const long long*)p)[idx];
    return ((const int*)p)[idx];
}

__global__ void hist_kernel(const void* edges, int E) {
    int e = blockIdx.x * blockDim.x + threadIdx.x;
    if (e < E) {
        int d = edge_val(edges, (long long)E + e);
        atomicAdd(&g_cnt[d], 1);
    }
}

// ---------------------------------------------------------------------------
// Multi-block scan.
// ---------------------------------------------------------------------------
__global__ __launch_bounds__(SCAN_B) void scanA_kernel(int n) {
    __shared__ int wsum[32];
    int gid = blockIdx.x * SCAN_B + threadIdx.x;
    int lane = threadIdx.x & 31;
    int wid = threadIdx.x >> 5;

    int c = (gid < n) ? g_cnt[gid] : 0;
    if (gid < n) g_dinv[gid] = rsqrtf((float)(c + 1));

    int v = c;
#pragma unroll
    for (int o = 1; o < 32; o <<= 1) {
        int u = __shfl_up_sync(0xffffffffu, v, o);
        if (lane >= o) v += u;
    }
    if (lane == 31) wsum[wid] = v;
    __syncthreads();
    if (wid == 0) {
        int w = (lane < SCAN_B / 32) ? wsum[lane] : 0;
#pragma unroll
        for (int o = 1; o < 32; o <<= 1) {
            int u = __shfl_up_sync(0xffffffffu, w, o);
            if (lane >= o) w += u;
        }
        wsum[lane] = w;
    }
    __syncthreads();
    int base = (wid == 0) ? 0 : wsum[wid - 1];
    int excl = base + v - c;
    if (gid < n) g_off[gid] = excl;
    if (threadIdx.x == SCAN_B - 1) g_bsum[blockIdx.x] = base + v;
}

__global__ void scanB_kernel(int n, int E) {
    int lane = threadIdx.x;
    __shared__ int buf[64];
    buf[lane] = (lane < SCAN_GRID) ? g_bsum[lane] : 0;
    __syncthreads();
    if (lane == 0) {
        int run = 0;
        for (int i = 0; i < 64; i++) { int t = buf[i]; buf[i] = run; run += t; }
    }
    __syncthreads();
    if (lane < SCAN_GRID) g_bsum[lane] = buf[lane];
    if (lane == 0) g_off[n] = E;
}

__global__ __launch_bounds__(SCAN_B) void scanC_kernel(int n) {
    int gid = blockIdx.x * SCAN_B + threadIdx.x;
    if (gid < n && blockIdx.x > 0) g_off[gid] += g_bsum[blockIdx.x];
}

__global__ void scatter_kernel(const void* edges, int E) {
    int e = blockIdx.x * blockDim.x + threadIdx.x;
    if (e < E) {
        int d = edge_val(edges, (long long)E + e);
        int s = edge_val(edges, e);
        int pos = g_off[d] + atomicAdd(&g_cur[d], 1);
        g_srcs[pos] = s;
    }
}

// ---------------------------------------------------------------------------
// Packed-f32x2 helpers (Blackwell FFMA2: only reachable via PTX).
// ---------------------------------------------------------------------------
__device__ __forceinline__ void ffma2(unsigned long long& acc,
                                      unsigned long long a,
                                      unsigned long long b) {
    asm("fma.rn.f32x2 %0, %1, %2, %0;" : "+l"(acc) : "l"(a), "l"(b));
}
__device__ __forceinline__ unsigned long long pack2(float v) {
    unsigned long long r;
    asm("mov.b64 %0, {%1, %1};" : "=l"(r) : "f"(v));
    return r;
}

// ---------------------------------------------------------------------------
// Tiled SGEMM: C[M,N] = (A[M,128] @ B[128,N]) * dinv[row]
// Accumulators packed across row pairs: acc2[i2][j] = (C[r0+2*i2][j], C[r0+2*i2+1][j]).
// ---------------------------------------------------------------------------
template <int BN, int TN>
__global__ __launch_bounds__(256) void gemm_scale_kernel(
    const float* __restrict__ A, const float* __restrict__ B,
    float* __restrict__ C, int M, int N)
{
    constexpr int BM = 128, BK = 16, TM = 8, K = 128;
    constexpr int THREADS = (BM / TM) * (BN / TN);
    __shared__ float As[BK][BM];   // As[k][m] — row pairs contiguous in m
    __shared__ float Bs[BK][BN];

    const int block_row = blockIdx.x * BM;
    const int tid = threadIdx.x;
    const int tcol = tid % (BN / TN);
    const int trow = tid / (BN / TN);

    unsigned long long acc2[TM / 2][TN];
#pragma unroll
    for (int i = 0; i < TM / 2; i++)
#pragma unroll
        for (int j = 0; j < TN; j++) acc2[i][j] = 0ull;

    for (int kt = 0; kt < K; kt += BK) {
        constexpr int A_f4 = BM * BK / 4;
#pragma unroll
        for (int i = tid; i < A_f4; i += THREADS) {
            int r  = i / (BK / 4);
            int c4 = i % (BK / 4);
            float4 v = make_float4(0.f, 0.f, 0.f, 0.f);
            if (block_row + r < M)
                v = *(const float4*)&A[(size_t)(block_row + r) * K + kt + c4 * 4];
            As[c4 * 4 + 0][r] = v.x;
            As[c4 * 4 + 1][r] = v.y;
            As[c4 * 4 + 2][r] = v.z;
            As[c4 * 4 + 3][r] = v.w;
        }
        constexpr int B_f4 = BK * BN / 4;
#pragma unroll
        for (int i = tid; i < B_f4; i += THREADS) {
            int r  = i / (BN / 4);
            int c4 = i % (BN / 4);
            *(float4*)&Bs[r][c4 * 4] = *(const float4*)&B[(size_t)(kt + r) * N + c4 * 4];
        }
        __syncthreads();
#pragma unroll
        for (int kk = 0; kk < BK; kk++) {
            // A row-pairs: contiguous, 8B-aligned (trow*TM is a multiple of 8)
            unsigned long long a2[TM / 2];
#pragma unroll
            for (int i = 0; i < TM / 2; i++)
                a2[i] = *(const unsigned long long*)&As[kk][trow * TM + i * 2];
            // B broadcast packs
            unsigned long long b2[TN];
#pragma unroll
            for (int j = 0; j < TN; j++)
                b2[j] = pack2(Bs[kk][tcol * TN + j]);
#pragma unroll
            for (int i = 0; i < TM / 2; i++)
#pragma unroll
                for (int j = 0; j < TN; j++)
                    ffma2(acc2[i][j], a2[i], b2[j]);
        }
        __syncthreads();
    }

#pragma unroll
    for (int i = 0; i < TM / 2; i++) {
#pragma unroll
        for (int half = 0; half < 2; half++) {
            int r = block_row + trow * TM + i * 2 + half;
            if (r >= M) continue;
            float s = g_dinv[r];
#pragma unroll
            for (int j = 0; j < TN; j += 4) {
                float4 v;
                float2 p0 = *(float2*)&acc2[i][j + 0];
                float2 p1 = *(float2*)&acc2[i][j + 1];
                float2 p2 = *(float2*)&acc2[i][j + 2];
                float2 p3 = *(float2*)&acc2[i][j + 3];
                v.x = (half ? p0.y : p0.x) * s;
                v.y = (half ? p1.y : p1.x) * s;
                v.z = (half ? p2.y : p2.x) * s;
                v.w = (half ? p3.y : p3.x) * s;
                *(float4*)&C[(size_t)r * N + tcol * TN + j] = v;
            }
        }
    }
}

// ---------------------------------------------------------------------------
// Warp-per-node aggregation.
// ---------------------------------------------------------------------------
template <bool RELU>
__global__ void aggregate128_kernel(const float* __restrict__ g,
                                    const float* __restrict__ bias,
                                    float* __restrict__ out, int n)
{
    int warp = (blockIdx.x * blockDim.x + threadIdx.x) >> 5;
    if (warp >= n) return;
    int lane = threadIdx.x & 31;
    const float4* g4 = (const float4*)g;

    float4 acc = g4[(size_t)warp * 32 + lane];   // self-loop term
    int e = g_off[warp];
    int end = g_off[warp + 1];
    while (e < end) {
        int m = min(32, end - e);
        int s = (lane < m) ? g_srcs[e + lane] : 0;
#pragma unroll 4
        for (int j = 0; j < m; j++) {
            int sj = __shfl_sync(0xffffffffu, s, j);
            float4 v = g4[(size_t)sj * 32 + lane];
            acc.x += v.x; acc.y += v.y; acc.z += v.z; acc.w += v.w;
        }
        e += m;
    }
    float sc = g_dinv[warp];
    float4 bv = ((const float4*)bias)[lane];
    float4 o;
    o.x = acc.x * sc + bv.x;
    o.y = acc.y * sc + bv.y;
    o.z = acc.z * sc + bv.z;
    o.w = acc.w * sc + bv.w;
    if (RELU) {
        o.x = fmaxf(o.x, 0.f); o.y = fmaxf(o.y, 0.f);
        o.z = fmaxf(o.z, 0.f); o.w = fmaxf(o.w, 0.f);
    }
    ((float4*)out)[(size_t)warp * 32 + lane] = o;
}

__global__ void aggregate64_kernel(const float* __restrict__ g,
                                   const float* __restrict__ bias,
                                   float* __restrict__ out, int n)
{
    int warp = (blockIdx.x * blockDim.x + threadIdx.x) >> 5;
    if (warp >= n) return;
    int lane = threadIdx.x & 31;
    const float2* g2 = (const float2*)g;

    float2 acc = g2[(size_t)warp * 32 + lane];
    int e = g_off[warp];
    int end = g_off[warp + 1];
    while (e < end) {
        int m = min(32, end - e);
        int s = (lane < m) ? g_srcs[e + lane] : 0;
#pragma unroll 4
        for (int j = 0; j < m; j++) {
            int sj = __shfl_sync(0xffffffffu, s, j);
            float2 v = g2[(size_t)sj * 32 + lane];
            acc.x += v.x; acc.y += v.y;
        }
        e += m;
    }
    float sc = g_dinv[warp];
    float2 bv = ((const float2*)bias)[lane];
    float2 o;
    o.x = acc.x * sc + bv.x;
    o.y = acc.y * sc + bv.y;
    ((float2*)out)[(size_t)warp * 32 + lane] = o;
}

// ---------------------------------------------------------------------------
extern "C" void kernel_launch(void* const* d_in, const int* in_sizes, int n_in,
                              void* d_out, int out_size) {
    const float* x  = (const float*)d_in[0];
    const void*  ei = d_in[1];
    const float* W1 = (const float*)d_in[2];
    const float* b1 = (const float*)d_in[3];
    const float* W2 = (const float*)d_in[4];
    const float* b2 = (const float*)d_in[5];
    const float* W3 = (const float*)d_in[6];
    const float* b3 = (const float*)d_in[7];
    float* out = (float*)d_out;

    const int n = in_sizes[0] / 128;   // 50000
    const int E = in_sizes[1] / 2;     // 800000

    float *h = nullptr, *t = nullptr;
    cudaGetSymbolAddress((void**)&h, g_h);
    cudaGetSymbolAddress((void**)&t, g_t);

    // ---- CSR build ----
    init_kernel<<<(n + 255) / 256, 256>>>(n);
    detect_kernel<<<1, 256>>>(ei, E);
    hist_kernel<<<(E + 255) / 256, 256>>>(ei, E);
    scanA_kernel<<<SCAN_GRID, SCAN_B>>>(n);
    scanB_kernel<<<1, 64>>>(n, E);
    scanC_kernel<<<SCAN_GRID, SCAN_B>>>(n);
    scatter_kernel<<<(E + 255) / 256, 256>>>(ei, E);

    const int gx = (n + 127) / 128;
    const int agg_blocks = (n * 32 + 255) / 256;

    // ---- layer 1 ----
    gemm_scale_kernel<128, 8><<<dim3(gx, 1), 256>>>(x, W1, h, n, 128);
    aggregate128_kernel<true><<<agg_blocks, 256>>>(h, b1, t, n);
    // ---- layer 2 ----
    gemm_scale_kernel<128, 8><<<dim3(gx, 1), 256>>>(t, W2, h, n, 128);
    aggregate128_kernel<true><<<agg_blocks, 256>>>(h, b2, t, n);
    // ---- layer 3 ----
    gemm_scale_kernel<64, 4><<<dim3(gx, 1), 256>>>(t, W3, h, n, 64);
    aggregate64_kernel<<<agg_blocks, 256>>>(h, b3, out, n);
}